// round 3
// baseline (speedup 1.0000x reference)
#include <cuda_runtime.h>
#include <stdint.h>

// Padded coordinate table: one float4 per atom, 16B-aligned -> every gather is
// a single LDG.E.128 hitting exactly one 32B L2 sector.
#define MAX_ATOMS 100352
__device__ float4 g_R4[MAX_ATOMS];

__global__ void pad_R_kernel(const float* __restrict__ R, int n_atoms) {
    int i = blockIdx.x * blockDim.x + threadIdx.x;
    if (i < n_atoms) {
        g_R4[i] = make_float4(R[3 * i + 0], R[3 * i + 1], R[3 * i + 2], 0.0f);
    }
}

__device__ __forceinline__ float edge_dist(int i, int j) {
    float4 a = g_R4[i];
    float4 b = g_R4[j];
    float dx = a.x - b.x;
    float dy = a.y - b.y;
    float dz = a.z - b.z;
    return sqrtf(dx * dx + dy * dy + dz * dz);
}

// 8 edges per thread: two int4 loads per index array (16B each),
// 16 independent gathers in flight, two float4 stores.
__global__ void dist_kernel(const int* __restrict__ idx_i,
                            const int* __restrict__ idx_j,
                            float* __restrict__ out,
                            int n_edges) {
    long long t = (long long)blockIdx.x * blockDim.x + threadIdx.x;
    long long base = t * 8;

    if (base + 8 <= (long long)n_edges) {
        const int4* pi = reinterpret_cast<const int4*>(idx_i + base);
        const int4* pj = reinterpret_cast<const int4*>(idx_j + base);
        int4 i0 = pi[0];
        int4 i1 = pi[1];
        int4 j0 = pj[0];
        int4 j1 = pj[1];

        float4 r0, r1;
        r0.x = edge_dist(i0.x, j0.x);
        r0.y = edge_dist(i0.y, j0.y);
        r0.z = edge_dist(i0.z, j0.z);
        r0.w = edge_dist(i0.w, j0.w);
        r1.x = edge_dist(i1.x, j1.x);
        r1.y = edge_dist(i1.y, j1.y);
        r1.z = edge_dist(i1.z, j1.z);
        r1.w = edge_dist(i1.w, j1.w);

        reinterpret_cast<float4*>(out + base)[0] = r0;
        reinterpret_cast<float4*>(out + base)[1] = r1;
    } else if (base < (long long)n_edges) {
        for (long long e = base; e < (long long)n_edges; ++e) {
            out[e] = edge_dist(idx_i[e], idx_j[e]);
        }
    }
}

extern "C" void kernel_launch(void* const* d_in, const int* in_sizes, int n_in,
                              void* d_out, int out_size) {
    const float* R         = (const float*)d_in[0];
    const int* idx_i       = (const int*)d_in[1];
    const int* idx_j       = (const int*)d_in[2];
    float* out             = (float*)d_out;

    int n_atoms = in_sizes[0] / 3;
    int n_edges = in_sizes[1];

    {
        int threads = 256;
        int blocks = (n_atoms + threads - 1) / threads;
        pad_R_kernel<<<blocks, threads>>>(R, n_atoms);
    }
    {
        int threads = 256;
        int edges_per_block = threads * 8;
        int blocks = (n_edges + edges_per_block - 1) / edges_per_block;
        dist_kernel<<<blocks, threads>>>(idx_i, idx_j, out, n_edges);
    }
}

// round 7
// speedup vs baseline: 1.0229x; 1.0229x over previous
#include <cuda_runtime.h>
#include <stdint.h>

// Padded coordinate table: one float4 per atom, 16B-aligned -> every gather is
// a single LDG.E.128 hitting exactly one 32B L2 sector.
#define MAX_ATOMS 100352
__device__ float4 g_R4[MAX_ATOMS];

__global__ void pad_R_kernel(const float* __restrict__ R, int n_atoms) {
    int i = blockIdx.x * blockDim.x + threadIdx.x;
    if (i < n_atoms) {
        g_R4[i] = make_float4(R[3 * i + 0], R[3 * i + 1], R[3 * i + 2], 0.0f);
    }
}

// Streaming int4 load that does NOT allocate in L1 (keeps L1 for the R4 table).
__device__ __forceinline__ int4 ld_stream_int4(const int4* p) {
    int4 v;
    asm volatile("ld.global.nc.L1::no_allocate.v4.b32 {%0,%1,%2,%3}, [%4];"
                 : "=r"(v.x), "=r"(v.y), "=r"(v.z), "=r"(v.w)
                 : "l"(p));
    return v;
}

// Streaming store, evict-first (no L1 pollution).
__device__ __forceinline__ void st_stream_float4(float4* p, float4 v) {
    asm volatile("st.global.cs.v4.f32 [%0], {%1,%2,%3,%4};"
                 :
                 : "l"(p), "f"(v.x), "f"(v.y), "f"(v.z), "f"(v.w)
                 : "memory");
}

__device__ __forceinline__ float edge_dist(int i, int j) {
    float4 a = g_R4[i];
    float4 b = g_R4[j];
    float dx = a.x - b.x;
    float dy = a.y - b.y;
    float dz = a.z - b.z;
    return sqrtf(dx * dx + dy * dy + dz * dz);
}

// 8 edges per thread: two int4 streaming loads per index array,
// 16 independent gathers in flight, two streaming float4 stores.
__global__ void dist_kernel(const int* __restrict__ idx_i,
                            const int* __restrict__ idx_j,
                            float* __restrict__ out,
                            int n_edges) {
    unsigned t = blockIdx.x * blockDim.x + threadIdx.x;
    unsigned base = t * 8u;

    if (base + 8u <= (unsigned)n_edges) {
        const int4* pi = reinterpret_cast<const int4*>(idx_i + base);
        const int4* pj = reinterpret_cast<const int4*>(idx_j + base);
        int4 i0 = ld_stream_int4(pi + 0);
        int4 i1 = ld_stream_int4(pi + 1);
        int4 j0 = ld_stream_int4(pj + 0);
        int4 j1 = ld_stream_int4(pj + 1);

        float4 r0, r1;
        r0.x = edge_dist(i0.x, j0.x);
        r0.y = edge_dist(i0.y, j0.y);
        r0.z = edge_dist(i0.z, j0.z);
        r0.w = edge_dist(i0.w, j0.w);
        r1.x = edge_dist(i1.x, j1.x);
        r1.y = edge_dist(i1.y, j1.y);
        r1.z = edge_dist(i1.z, j1.z);
        r1.w = edge_dist(i1.w, j1.w);

        st_stream_float4(reinterpret_cast<float4*>(out + base) + 0, r0);
        st_stream_float4(reinterpret_cast<float4*>(out + base) + 1, r1);
    } else if (base < (unsigned)n_edges) {
        for (unsigned e = base; e < (unsigned)n_edges; ++e) {
            out[e] = edge_dist(idx_i[e], idx_j[e]);
        }
    }
}

extern "C" void kernel_launch(void* const* d_in, const int* in_sizes, int n_in,
                              void* d_out, int out_size) {
    const float* R   = (const float*)d_in[0];
    const int* idx_i = (const int*)d_in[1];
    const int* idx_j = (const int*)d_in[2];
    float* out       = (float*)d_out;

    int n_atoms = in_sizes[0] / 3;
    int n_edges = in_sizes[1];

    {
        int threads = 256;
        int blocks = (n_atoms + threads - 1) / threads;
        pad_R_kernel<<<blocks, threads>>>(R, n_atoms);
    }
    {
        int threads = 256;
        int edges_per_block = threads * 8;
        int blocks = (n_edges + edges_per_block - 1) / edges_per_block;
        dist_kernel<<<blocks, threads>>>(idx_i, idx_j, out, n_edges);
    }
}